// round 6
// baseline (speedup 1.0000x reference)
#include <cuda_runtime.h>
#include <cuda_fp16.h>

// LBP forward: out = 7.5 + 0.5 * sum_p 2^p * tanh(5*(samp_p - cen_p))
// Thread = (n, f, row-pair rp, 8-wide span ws): 16 outputs.
// Per tap: center/sample are the SAME channel shifted by (dy,dx) in {-1,0,1}^2.
//   dy=0: sample rows are the center registers (0 extra loads)
//   dy=+-1: one row shared with a center reg, one extra 8-wide row load
//   dx=+-1: ONE edge scalar per sample row; intra-window shift is reg select.
// Math: diff in f32, then half2 HMUL/tanh.approx.f16x2/HFMA2 accumulate.

#define N_  32
#define D_  64
#define H_  56
#define W_  56
#define F_  128
#define P_  4
#define HW_ (H_ * W_)
#define WS_ 7                      // 8-wide spans per row
#define RP_ 28                     // row pairs
#define TOTAL_ (N_ * F_ * RP_ * WS_)   // 802,816 threads

struct F8 { float4 a, b; };

__device__ __forceinline__ F8 load8(const float* __restrict__ p) {
    F8 r;
    r.a = *reinterpret_cast<const float4*>(p);
    r.b = *reinterpret_cast<const float4*>(p + 4);
    return r;
}
__device__ __forceinline__ F8 zero8() {
    F8 r; r.a = make_float4(0.f,0.f,0.f,0.f); r.b = r.a; return r;
}
// shift window one left (sample at w-1..w+6): [e,a.x,a.y,a.z | a.w,b.x,b.y,b.z]
__device__ __forceinline__ F8 shl8(const F8& t, float e) {
    F8 r;
    r.a = make_float4(e,   t.a.x, t.a.y, t.a.z);
    r.b = make_float4(t.a.w, t.b.x, t.b.y, t.b.z);
    return r;
}
// shift window one right (sample at w+1..w+8): [a.y,a.z,a.w,b.x | b.y,b.z,b.w,e]
__device__ __forceinline__ F8 shr8(const F8& t, float e) {
    F8 r;
    r.a = make_float4(t.a.y, t.a.z, t.a.w, t.b.x);
    r.b = make_float4(t.b.y, t.b.z, t.b.w, e);
    return r;
}

__device__ __forceinline__ __half2 tanh_h2(__half2 x) {
    unsigned v = *reinterpret_cast<unsigned*>(&x);
    asm("tanh.approx.f16x2 %0, %0;" : "+r"(v));
    return *reinterpret_cast<__half2*>(&v);
}

__device__ __forceinline__ void emit8(const F8& c, const F8& s, __half2 wp2,
                                      __half2* acc) {
    const __half2 five = __floats2half2_rn(5.f, 5.f);
    __half2 d0 = __floats2half2_rn(s.a.x - c.a.x, s.a.y - c.a.y);
    __half2 d1 = __floats2half2_rn(s.a.z - c.a.z, s.a.w - c.a.w);
    __half2 d2 = __floats2half2_rn(s.b.x - c.b.x, s.b.y - c.b.y);
    __half2 d3 = __floats2half2_rn(s.b.z - c.b.z, s.b.w - c.b.w);
    acc[0] = __hfma2(wp2, tanh_h2(__hmul2(d0, five)), acc[0]);
    acc[1] = __hfma2(wp2, tanh_h2(__hmul2(d1, five)), acc[1]);
    acc[2] = __hfma2(wp2, tanh_h2(__hmul2(d2, five)), acc[2]);
    acc[3] = __hfma2(wp2, tanh_h2(__hmul2(d3, five)), acc[3]);
}

__global__ __launch_bounds__(128) void lbp_w8_kernel(
    const float* __restrict__ in,
    const int*   __restrict__ kern,   // (F,P,2)
    const int*   __restrict__ pm,     // (F,P)
    float*       __restrict__ out)
{
    int idx = blockIdx.x * 128 + threadIdx.x;
    if (idx >= TOTAL_) return;

    int ws = idx % WS_;
    int t  = idx / WS_;
    int rp = t % RP_;
    t /= RP_;
    int f  = t & (F_ - 1);
    int n  = t >> 7;

    int r0 = rp * 2, r1 = r0 + 1;
    int w  = ws * 8;

    int4 pmv = *reinterpret_cast<const int4*>(pm + f * P_);
    int4 k01 = *reinterpret_cast<const int4*>(kern + f * P_ * 2);
    int4 k23 = *reinterpret_cast<const int4*>(kern + f * P_ * 2 + 4);
    int cs[4]  = {pmv.x, pmv.y, pmv.z, pmv.w};
    int dys[4] = {k01.x - 1, k01.z - 1, k23.x - 1, k23.z - 1};
    int dxs[4] = {k01.y - 1, k01.w - 1, k23.y - 1, k23.w - 1};

    const float* __restrict__ base = in + (size_t)n * D_ * HW_;

    __half2 z = __floats2half2_rn(0.f, 0.f);
    __half2 acc0[4] = {z, z, z, z};
    __half2 acc1[4] = {z, z, z, z};

#pragma unroll
    for (int p = 0; p < P_; p++) {
        const float* __restrict__ pl = base + cs[p] * HW_;
        int dy = dys[p], dx = dxs[p];

        F8 c0 = load8(pl + r0 * W_ + w);
        F8 c1 = load8(pl + r1 * W_ + w);

        // pre-shift sample rows
        F8 t0, t1;
        bool v0 = true, v1 = true;       // sample-row validity (for edge scalars)
        if (dy == 0) {
            t0 = c0; t1 = c1;
        } else if (dy < 0) {
            t1 = c0;
            v0 = (r0 > 0);
            t0 = v0 ? load8(pl + (r0 - 1) * W_ + w) : zero8();
        } else {
            t0 = c1;
            v1 = (r1 + 1 < H_);
            t1 = v1 ? load8(pl + (r1 + 1) * W_ + w) : zero8();
        }

        F8 s0, s1;
        if (dx == 0) {
            s0 = t0; s1 = t1;
        } else {
            int sr0 = r0 + dy, sr1 = r1 + dy;
            if (dx < 0) {
                float e0 = (v0 && w > 0) ? __ldg(pl + sr0 * W_ + w - 1) : 0.f;
                float e1 = (v1 && w > 0) ? __ldg(pl + sr1 * W_ + w - 1) : 0.f;
                s0 = shl8(t0, e0); s1 = shl8(t1, e1);
            } else {
                float e0 = (v0 && w + 8 < W_) ? __ldg(pl + sr0 * W_ + w + 8) : 0.f;
                float e1 = (v1 && w + 8 < W_) ? __ldg(pl + sr1 * W_ + w + 8) : 0.f;
                s0 = shr8(t0, e0); s1 = shr8(t1, e1);
            }
        }

        float wpf = 0.5f * (float)(1 << p);
        __half2 wp2 = __floats2half2_rn(wpf, wpf);
        emit8(c0, s0, wp2, acc0);
        emit8(c1, s1, wp2, acc1);
    }

    float* o = out + ((size_t)(n * F_ + f) * HW_ + r0 * W_ + w);
#pragma unroll
    for (int r = 0; r < 2; r++) {
        __half2* a = r ? acc1 : acc0;
        float* orow = o + r * W_;
        float2 v0 = __half22float2(a[0]), v1 = __half22float2(a[1]);
        float2 v2 = __half22float2(a[2]), v3 = __half22float2(a[3]);
        *reinterpret_cast<float4*>(orow) =
            make_float4(7.5f + v0.x, 7.5f + v0.y, 7.5f + v1.x, 7.5f + v1.y);
        *reinterpret_cast<float4*>(orow + 4) =
            make_float4(7.5f + v2.x, 7.5f + v2.y, 7.5f + v3.x, 7.5f + v3.y);
    }
}

extern "C" void kernel_launch(void* const* d_in, const int* in_sizes, int n_in,
                              void* d_out, int out_size)
{
    const float* in   = (const float*)d_in[0];
    const int*   kern = (const int*)d_in[1];
    const int*   pm   = (const int*)d_in[2];
    float*       out  = (float*)d_out;

    int blocks = (TOTAL_ + 127) / 128;   // 6272
    lbp_w8_kernel<<<blocks, 128>>>(in, kern, pm, out);
}